// round 1
// baseline (speedup 1.0000x reference)
#include <cuda_runtime.h>

#define H       64
#define NSEG    1024
#define MMAX    400000
#define LPB     512      // lanes per block in pooling kernel
#define POOL_T  192      // threads in pooling kernel = 3*H features

// ---------------- scratch (no allocations allowed) ----------------
__device__ float g_scores[MMAX];       // pass1: score; pass2: exp(score - segmax)
__device__ float g_seg_max[NSEG];
__device__ float g_seg_sum[NSEG + 1];  // +1 = dump slot for out-of-range lanes

// ---------------- helpers ----------------
__device__ __forceinline__ void atomicMaxFloat(float* addr, float value) {
    if (value >= 0.0f)
        atomicMax((int*)addr, __float_as_int(value));
    else
        atomicMin((unsigned int*)addr, __float_as_uint(value));
}

// ---------------- kernel 0: init ----------------
__global__ void init_kernel(float* __restrict__ out, int out_size) {
    int i = blockIdx.x * blockDim.x + threadIdx.x;
    if (i < out_size) out[i] = 0.0f;
    if (i < NSEG) g_seg_max[i] = __int_as_float(0xff800000);  // -inf
    if (i <= NSEG) g_seg_sum[i] = 0.0f;
}

// ---------------- kernel 1: MLP score + per-segment max ----------------
__global__ __launch_bounds__(256) void score_kernel(
    const float* __restrict__ ht, const float* __restrict__ info,
    const int* __restrict__ seg,
    const float* __restrict__ w1, const float* __restrict__ b1,
    const float* __restrict__ w2, const float* __restrict__ b2, int M)
{
    __shared__ float w1s[128 * 16];
    __shared__ float b1s[16], w2s[16];
    __shared__ float b2s;

    for (int i = threadIdx.x; i < 128 * 16; i += blockDim.x) w1s[i] = w1[i];
    if (threadIdx.x < 16) { b1s[threadIdx.x] = b1[threadIdx.x]; w2s[threadIdx.x] = w2[threadIdx.x]; }
    if (threadIdx.x == 0) b2s = b2[0];
    __syncthreads();

    int lane = blockIdx.x * blockDim.x + threadIdx.x;
    if (lane >= M) return;

    float h[16];
#pragma unroll
    for (int j = 0; j < 16; j++) h[j] = b1s[j];

#pragma unroll
    for (int half = 0; half < 2; half++) {
        const float4* x4 = reinterpret_cast<const float4*>(half ? info : ht)
                         + (size_t)lane * (H / 4);
#pragma unroll
        for (int kk = 0; kk < H / 4; kk++) {
            float4 xv = x4[kk];
            int kbase = half * H + kk * 4;
#pragma unroll
            for (int c = 0; c < 4; c++) {
                float x = (&xv.x)[c];
                const float4* wr = reinterpret_cast<const float4*>(&w1s[(kbase + c) * 16]);
#pragma unroll
                for (int q = 0; q < 4; q++) {
                    float4 w = wr[q];
                    h[q * 4 + 0] = fmaf(x, w.x, h[q * 4 + 0]);
                    h[q * 4 + 1] = fmaf(x, w.y, h[q * 4 + 1]);
                    h[q * 4 + 2] = fmaf(x, w.z, h[q * 4 + 2]);
                    h[q * 4 + 3] = fmaf(x, w.w, h[q * 4 + 3]);
                }
            }
        }
    }

    float s = b2s;
#pragma unroll
    for (int j = 0; j < 16; j++) s = fmaf(fmaxf(h[j], 0.0f), w2s[j], s);

    g_scores[lane] = s;
    atomicMaxFloat(&g_seg_max[seg[lane]], s);
}

// ---------------- kernel 2: exp + per-segment sum (warp-segmented reduce) ----
__global__ __launch_bounds__(256) void expsum_kernel(
    const int* __restrict__ seg, int M)
{
    int lane = blockIdx.x * blockDim.x + threadIdx.x;
    int li = threadIdx.x & 31;

    int s;
    float ex;
    if (lane < M) {
        s = seg[lane];
        ex = expf(g_scores[lane] - g_seg_max[s]);
        g_scores[lane] = ex;           // overwrite score with exp value
    } else {
        s = NSEG;                      // dump slot
        ex = 0.0f;
    }

    // segment ids are sorted -> runs are contiguous; segmented suffix-reduce
    float v = ex;
#pragma unroll
    for (int o = 1; o < 32; o <<= 1) {
        float u  = __shfl_down_sync(0xffffffffu, v, o);
        int   s2 = __shfl_down_sync(0xffffffffu, s, o);
        if (li + o < 32 && s2 == s) v += u;
    }
    int sp = __shfl_up_sync(0xffffffffu, s, 1);
    if (li == 0 || sp != s)
        atomicAdd(&g_seg_sum[s], v);
}

// ---------------- kernel 3: weighted pooling into [NSEG, 192] --------------
__global__ __launch_bounds__(POOL_T) void pool_kernel(
    const float* __restrict__ ht, const float* __restrict__ info,
    const float* __restrict__ fut, const int* __restrict__ seg,
    float* __restrict__ out, int M)
{
    __shared__ float prob_s[LPB];
    __shared__ int   seg_s[LPB];

    int base = blockIdx.x * LPB;
    int nl = M - base;
    if (nl > LPB) nl = LPB;

    for (int i = threadIdx.x; i < nl; i += blockDim.x) {
        int s = seg[base + i];
        seg_s[i] = s;
        prob_s[i] = g_scores[base + i] / g_seg_sum[s];
    }
    __syncthreads();

    int t = threadIdx.x;   // 0..191 -> output feature column
    const float* src;
    if (t < 64)       src = ht  + t;
    else if (t < 128) src = info + (t - 64);
    else              src = fut + (t - 128);
    src += (size_t)base * H;

    float acc = 0.0f;
    int cur = seg_s[0];
#pragma unroll 8
    for (int i = 0; i < nl; i++) {
        int s = seg_s[i];
        if (s != cur) {                      // uniform across block
            atomicAdd(&out[cur * 192 + t], acc);
            acc = 0.0f;
            cur = s;
        }
        acc = fmaf(prob_s[i], src[(size_t)i * H], acc);
    }
    atomicAdd(&out[cur * 192 + t], acc);
}

// ---------------- launch ----------------
extern "C" void kernel_launch(void* const* d_in, const int* in_sizes, int n_in,
                              void* d_out, int out_size)
{
    const float* ht   = (const float*)d_in[0];
    const float* info = (const float*)d_in[1];
    const float* fut  = (const float*)d_in[2];
    const int*   seg  = (const int*)  d_in[3];
    const float* w1   = (const float*)d_in[4];
    const float* b1   = (const float*)d_in[5];
    const float* w2   = (const float*)d_in[6];
    const float* b2   = (const float*)d_in[7];
    float* out = (float*)d_out;

    int M = in_sizes[0] / H;

    int init_n = out_size > (NSEG + 1) ? out_size : (NSEG + 1);
    init_kernel<<<(init_n + 255) / 256, 256>>>(out, out_size);

    score_kernel<<<(M + 255) / 256, 256>>>(ht, info, seg, w1, b1, w2, b2, M);
    expsum_kernel<<<(M + 255) / 256, 256>>>(seg, M);
    pool_kernel<<<(M + LPB - 1) / LPB, POOL_T>>>(ht, info, fut, seg, out, M);
}

// round 2
// speedup vs baseline: 1.2574x; 1.2574x over previous
#include <cuda_runtime.h>

#define H       64
#define NSEG    1024
#define LPB     192      // lanes per block (== threads: 1 lane/thread in score phase)
#define NWARP   (LPB / 32)

// ---------------- scratch (no allocations allowed) ----------------
__device__ float g_seg_sum[NSEG + 1];  // +1 = dump slot for out-of-range lanes

// ---------------- kernel 0: init ----------------
__global__ void init_kernel(float* __restrict__ out, int out_size) {
    int i = blockIdx.x * blockDim.x + threadIdx.x;
    if (i < out_size) out[i] = 0.0f;
    if (i <= NSEG) g_seg_sum[i] = 0.0f;
}

// ---------------- kernel 1: fused score + exp + seg-sum + unnormalized pool --
__global__ __launch_bounds__(LPB) void fused_kernel(
    const float* __restrict__ ht, const float* __restrict__ info,
    const float* __restrict__ fut, const int* __restrict__ seg,
    const float* __restrict__ w1, const float* __restrict__ b1,
    const float* __restrict__ w2, const float* __restrict__ b2,
    float* __restrict__ out, int M)
{
    __shared__ float w1s[128 * 16];
    __shared__ float b1s[16], w2s[16];
    __shared__ float b2s;
    __shared__ float ex_s[LPB];
    __shared__ int   seg_s[LPB];
    __shared__ int   run_start[LPB + 1];
    __shared__ int   warp_cnt[NWARP];
    __shared__ int   nruns_s;

    const int tid = threadIdx.x;
    const int base = blockIdx.x * LPB;
    int nl = M - base;
    if (nl > LPB) nl = LPB;

    // ---- load MLP weights ----
    for (int i = tid; i < 128 * 16; i += LPB) w1s[i] = w1[i];
    if (tid < 16) { b1s[tid] = b1[tid]; w2s[tid] = w2[tid]; }
    if (tid == 0) b2s = b2[0];
    __syncthreads();

    // ---- phase 1: per-lane MLP score -> ex = exp(score) (no max: scores tiny)
    const int lane = base + tid;
    float ex = 0.0f;
    int   s  = NSEG;                 // dump slot for OOB lanes
    if (tid < nl) {
        float h[16];
#pragma unroll
        for (int j = 0; j < 16; j++) h[j] = b1s[j];

#pragma unroll
        for (int half = 0; half < 2; half++) {
            const float4* x4 = reinterpret_cast<const float4*>(half ? info : ht)
                             + (size_t)lane * (H / 4);
#pragma unroll
            for (int kk = 0; kk < H / 4; kk++) {
                float4 xv = x4[kk];
                int kbase = half * H + kk * 4;
#pragma unroll
                for (int c = 0; c < 4; c++) {
                    float x = (&xv.x)[c];
                    const float4* wr = reinterpret_cast<const float4*>(&w1s[(kbase + c) * 16]);
#pragma unroll
                    for (int q = 0; q < 4; q++) {
                        float4 w = wr[q];
                        h[q * 4 + 0] = fmaf(x, w.x, h[q * 4 + 0]);
                        h[q * 4 + 1] = fmaf(x, w.y, h[q * 4 + 1]);
                        h[q * 4 + 2] = fmaf(x, w.z, h[q * 4 + 2]);
                        h[q * 4 + 3] = fmaf(x, w.w, h[q * 4 + 3]);
                    }
                }
            }
        }
        float sc = b2s;
#pragma unroll
        for (int j = 0; j < 16; j++) sc = fmaf(fmaxf(h[j], 0.0f), w2s[j], sc);

        s  = seg[lane];
        ex = expf(sc);
        seg_s[tid] = s;
    }
    ex_s[tid] = ex;

    // ---- per-segment sum of ex (sorted ids -> warp-segmented reduce) ----
    {
        const int li = tid & 31;
        float v = ex;
#pragma unroll
        for (int o = 1; o < 32; o <<= 1) {
            float u  = __shfl_down_sync(0xffffffffu, v, o);
            int   s2 = __shfl_down_sync(0xffffffffu, s, o);
            if (li + o < 32 && s2 == s) v += u;
        }
        int sp = __shfl_up_sync(0xffffffffu, s, 1);
        if ((li == 0 || sp != s) && v != 0.0f)
            atomicAdd(&g_seg_sum[s], v);
    }
    __syncthreads();

    // ---- build ordered run boundaries over [0, nl) ----
    int flag = 0;
    if (tid < nl) flag = (tid == 0) || (seg_s[tid] != seg_s[tid - 1]);
    unsigned m = __ballot_sync(0xffffffffu, flag);
    const int wid = tid >> 5, li = tid & 31;
    if (li == 0) warp_cnt[wid] = __popc(m);
    __syncthreads();
    if (tid == 0) {
        int tot = 0;
#pragma unroll
        for (int w = 0; w < NWARP; w++) { int c = warp_cnt[w]; warp_cnt[w] = tot; tot += c; }
        nruns_s = tot;
        run_start[tot] = nl;
    }
    __syncthreads();
    if (flag)
        run_start[warp_cnt[wid] + __popc(m & ((1u << li) - 1u))] = tid;
    __syncthreads();

    // ---- phase 2: unnormalized pooling, one feature column per thread ----
    // column t: 0..63 -> ht, 64..127 -> info, 128..191 -> fut
    const float* src;
    if (tid < 64)       src = ht   + tid;
    else if (tid < 128) src = info + (tid - 64);
    else                src = fut  + (tid - 128);
    src += (size_t)base * H;

    const int nruns = nruns_s;
    for (int r = 0; r < nruns; r++) {
        const int st = run_start[r];
        const int en = run_start[r + 1];
        const int sr = seg_s[st];
        float a0 = 0.f, a1 = 0.f, a2 = 0.f, a3 = 0.f;
        int i = st;
        for (; i + 4 <= en; i += 4) {
            a0 = fmaf(ex_s[i    ], src[(size_t)(i    ) * H], a0);
            a1 = fmaf(ex_s[i + 1], src[(size_t)(i + 1) * H], a1);
            a2 = fmaf(ex_s[i + 2], src[(size_t)(i + 2) * H], a2);
            a3 = fmaf(ex_s[i + 3], src[(size_t)(i + 3) * H], a3);
        }
        for (; i < en; i++)
            a0 = fmaf(ex_s[i], src[(size_t)i * H], a0);
        float acc = (a0 + a1) + (a2 + a3);
        atomicAdd(&out[sr * 192 + tid], acc);
    }
}

// ---------------- kernel 2: normalize out by seg_sum ----------------
__global__ void normalize_kernel(float* __restrict__ out) {
    int i = blockIdx.x * blockDim.x + threadIdx.x;   // i < NSEG*192
    if (i < NSEG * 192)
        out[i] /= g_seg_sum[i / 192];
}

// ---------------- launch ----------------
extern "C" void kernel_launch(void* const* d_in, const int* in_sizes, int n_in,
                              void* d_out, int out_size)
{
    const float* ht   = (const float*)d_in[0];
    const float* info = (const float*)d_in[1];
    const float* fut  = (const float*)d_in[2];
    const int*   seg  = (const int*)  d_in[3];
    const float* w1   = (const float*)d_in[4];
    const float* b1   = (const float*)d_in[5];
    const float* w2   = (const float*)d_in[6];
    const float* b2   = (const float*)d_in[7];
    float* out = (float*)d_out;

    int M = in_sizes[0] / H;

    int init_n = out_size > (NSEG + 1) ? out_size : (NSEG + 1);
    init_kernel<<<(init_n + 255) / 256, 256>>>(out, out_size);

    fused_kernel<<<(M + LPB - 1) / LPB, LPB>>>(ht, info, fut, seg,
                                               w1, b1, w2, b2, out, M);

    normalize_kernel<<<(NSEG * 192 + 255) / 256, 256>>>(out);
}